// round 6
// baseline (speedup 1.0000x reference)
#include <cuda_runtime.h>
#include <cuda_bf16.h>
#include <math.h>

// ---------------------------------------------------------------------------
// EnhancedHybridModel: conv stack -> FC -> 4-qubit sim -> head.  B = 1024.
// All intermediates in __device__ global scratch (no allocations).
// ---------------------------------------------------------------------------

#define B 1024
#define INVS 0.99999500003749968f   // 1/sqrt(1+1e-5)

__device__ float g_act1[B * 32 * 16 * 16];   // after conv1+pool   (32 MB)
__device__ float g_act2[B * 64 * 8 * 8];     // after conv2+pool   (16 MB)
__device__ float g_act3[B * 2048];           // after conv3+avgpool, flattened
__device__ float g_h512[B * 512];            // after FC1+ReLU
__device__ float2 g_Utot[16 * 16];           // total quantum unitary

// ---------------------------------------------------------------------------
// Kernel 1: conv1 (3->32, 32x32, pad1) + BN + ReLU + 2x2 maxpool -> [B,32,16,16]
// One block per image, 256 threads = 16x16 pooled positions.
// ---------------------------------------------------------------------------
__global__ __launch_bounds__(256) void conv1_k(
    const float* __restrict__ x, const float* __restrict__ w,
    const float* __restrict__ bias, const float* __restrict__ gam,
    const float* __restrict__ bet)
{
    __shared__ float sin_[3 * 34 * 34];
    __shared__ float sw_[32 * 27];
    __shared__ float sa[32], sd[32];

    const int img = blockIdx.x;
    const int tid = threadIdx.x;

    for (int i = tid; i < 3 * 34 * 34; i += 256) sin_[i] = 0.f;
    // 864 floats = 216 float4 (w base is allocation-aligned)
    if (tid < 216) ((float4*)sw_)[tid] = ((const float4*)w)[tid];
    if (tid < 32) {
        float a = gam[tid] * INVS;
        sa[tid] = a;
        sd[tid] = a * bias[tid] + bet[tid];
    }
    __syncthreads();

    const float* xp = x + (size_t)img * 3 * 32 * 32;
    for (int i = tid; i < 3 * 32 * 32; i += 256) {
        int c = i >> 10, y = (i >> 5) & 31, xx = i & 31;
        sin_[c * (34 * 34) + (y + 1) * 34 + (xx + 1)] = xp[i];
    }
    __syncthreads();

    const int py = tid >> 4, px = tid & 15;

    float patch[3][4][4];
#pragma unroll
    for (int c = 0; c < 3; c++)
#pragma unroll
        for (int dy = 0; dy < 4; dy++)
#pragma unroll
            for (int dx = 0; dx < 4; dx++)
                patch[c][dy][dx] = sin_[c * (34 * 34) + (2 * py + dy) * 34 + (2 * px + dx)];

    float* op = g_act1 + (size_t)img * 32 * 256 + py * 16 + px;

    for (int oc = 0; oc < 32; oc++) {
        float a0 = 0.f, a1 = 0.f, a2 = 0.f, a3 = 0.f;
        const float* wk = sw_ + oc * 27;
#pragma unroll
        for (int c = 0; c < 3; c++)
#pragma unroll
            for (int ky = 0; ky < 3; ky++)
#pragma unroll
                for (int kx = 0; kx < 3; kx++) {
                    float wv = wk[c * 9 + ky * 3 + kx];
                    a0 = fmaf(patch[c][ky][kx],         wv, a0);
                    a1 = fmaf(patch[c][ky][kx + 1],     wv, a1);
                    a2 = fmaf(patch[c][ky + 1][kx],     wv, a2);
                    a3 = fmaf(patch[c][ky + 1][kx + 1], wv, a3);
                }
        float a = sa[oc], d = sd[oc];
        float v0 = fmaxf(fmaf(a, a0, d), 0.f);
        float v1 = fmaxf(fmaf(a, a1, d), 0.f);
        float v2 = fmaxf(fmaf(a, a2, d), 0.f);
        float v3 = fmaxf(fmaf(a, a3, d), 0.f);
        op[oc * 256] = fmaxf(fmaxf(v0, v1), fmaxf(v2, v3));
    }
}

// ---------------------------------------------------------------------------
// Kernel 2: conv2 (32->64, 16x16, pad1) + BN + ReLU + maxpool -> [B,64,8,8]
// Grid (B, 2): 32 ocs/block. smem: input 41472B + weights [ic][oc][12] 49152B
// = 90624B -> 2 CTAs/SM. Weight rows padded 9->12 (48B, 16B-aligned):
// 2x LDS.128 + 1x LDS.32 per oc; patch reads via float2.
// 256 threads: pos = tid&63 (8x8 pooled), og = tid>>6 -> 8 ocs each.
// ---------------------------------------------------------------------------
__global__ __launch_bounds__(256) void conv2_k(
    const float* __restrict__ w, const float* __restrict__ bias,
    const float* __restrict__ gam, const float* __restrict__ bet)
{
    extern __shared__ float sm[];
    float* sin_ = sm;                 // 32*18*18 = 10368 floats
    float* swt  = sm + 10368;         // [ic][oc][12] = 32*32*12 = 12288 floats
    __shared__ float sa[32], sd[32];

    const int img = blockIdx.x;
    const int ocBase = blockIdx.y * 32;
    const int tid = threadIdx.x;

    for (int i = tid; i < 10368; i += 256) sin_[i] = 0.f;
    // stage weights transposed+padded: w[ocBase+oc][ic][kk] -> swt[ic][oc][12]
    for (int i = tid; i < 32 * 32 * 9; i += 256) {
        int oc = i / 288, rem = i - oc * 288;
        int ic = rem / 9, kk = rem - ic * 9;
        swt[ic * 384 + oc * 12 + kk] = w[(size_t)(ocBase + oc) * 288 + rem];
    }
    if (tid < 32) {
        int oc = ocBase + tid;
        float a = gam[oc] * INVS;
        sa[tid] = a;
        sd[tid] = a * bias[oc] + bet[oc];
    }
    __syncthreads();

    const float* ip = g_act1 + (size_t)img * 32 * 256;
    for (int i = tid; i < 32 * 256; i += 256) {
        int c = i >> 8, y = (i >> 4) & 15, xx = i & 15;
        sin_[c * 324 + (y + 1) * 18 + (xx + 1)] = ip[i];
    }
    __syncthreads();

    const int pos = tid & 63;
    const int py = pos >> 3, px = pos & 7;
    const int og = tid >> 6;          // 0..3, 8 ocs each

    float acc[8][4];
#pragma unroll
    for (int k = 0; k < 8; k++)
#pragma unroll
        for (int p = 0; p < 4; p++) acc[k][p] = 0.f;

    for (int ic = 0; ic < 32; ic++) {
        float p[4][4];
        const float* sp = sin_ + ic * 324 + (2 * py) * 18 + 2 * px;
#pragma unroll
        for (int dy = 0; dy < 4; dy++) {
            float2 v0 = *(const float2*)(sp + dy * 18);
            float2 v1 = *(const float2*)(sp + dy * 18 + 2);
            p[dy][0] = v0.x; p[dy][1] = v0.y; p[dy][2] = v1.x; p[dy][3] = v1.y;
        }

        const float* wp = swt + ic * 384 + (og * 8) * 12;
#pragma unroll
        for (int k = 0; k < 8; k++) {
            float4 w0 = *(const float4*)(wp + k * 12);
            float4 w1 = *(const float4*)(wp + k * 12 + 4);
            float  w8 = wp[k * 12 + 8];
            // row ky=0: w0.x w0.y w0.z ; ky=1: w0.w w1.x w1.y ; ky=2: w1.z w1.w w8
            acc[k][0] = fmaf(p[0][0], w0.x, acc[k][0]);
            acc[k][1] = fmaf(p[0][1], w0.x, acc[k][1]);
            acc[k][2] = fmaf(p[1][0], w0.x, acc[k][2]);
            acc[k][3] = fmaf(p[1][1], w0.x, acc[k][3]);
            acc[k][0] = fmaf(p[0][1], w0.y, acc[k][0]);
            acc[k][1] = fmaf(p[0][2], w0.y, acc[k][1]);
            acc[k][2] = fmaf(p[1][1], w0.y, acc[k][2]);
            acc[k][3] = fmaf(p[1][2], w0.y, acc[k][3]);
            acc[k][0] = fmaf(p[0][2], w0.z, acc[k][0]);
            acc[k][1] = fmaf(p[0][3], w0.z, acc[k][1]);
            acc[k][2] = fmaf(p[1][2], w0.z, acc[k][2]);
            acc[k][3] = fmaf(p[1][3], w0.z, acc[k][3]);

            acc[k][0] = fmaf(p[1][0], w0.w, acc[k][0]);
            acc[k][1] = fmaf(p[1][1], w0.w, acc[k][1]);
            acc[k][2] = fmaf(p[2][0], w0.w, acc[k][2]);
            acc[k][3] = fmaf(p[2][1], w0.w, acc[k][3]);
            acc[k][0] = fmaf(p[1][1], w1.x, acc[k][0]);
            acc[k][1] = fmaf(p[1][2], w1.x, acc[k][1]);
            acc[k][2] = fmaf(p[2][1], w1.x, acc[k][2]);
            acc[k][3] = fmaf(p[2][2], w1.x, acc[k][3]);
            acc[k][0] = fmaf(p[1][2], w1.y, acc[k][0]);
            acc[k][1] = fmaf(p[1][3], w1.y, acc[k][1]);
            acc[k][2] = fmaf(p[2][2], w1.y, acc[k][2]);
            acc[k][3] = fmaf(p[2][3], w1.y, acc[k][3]);

            acc[k][0] = fmaf(p[2][0], w1.z, acc[k][0]);
            acc[k][1] = fmaf(p[2][1], w1.z, acc[k][1]);
            acc[k][2] = fmaf(p[3][0], w1.z, acc[k][2]);
            acc[k][3] = fmaf(p[3][1], w1.z, acc[k][3]);
            acc[k][0] = fmaf(p[2][1], w1.w, acc[k][0]);
            acc[k][1] = fmaf(p[2][2], w1.w, acc[k][1]);
            acc[k][2] = fmaf(p[3][1], w1.w, acc[k][2]);
            acc[k][3] = fmaf(p[3][2], w1.w, acc[k][3]);
            acc[k][0] = fmaf(p[2][2], w8, acc[k][0]);
            acc[k][1] = fmaf(p[2][3], w8, acc[k][1]);
            acc[k][2] = fmaf(p[3][2], w8, acc[k][2]);
            acc[k][3] = fmaf(p[3][3], w8, acc[k][3]);
        }
    }

    float* op = g_act2 + (size_t)img * 64 * 64 + pos;
#pragma unroll
    for (int k = 0; k < 8; k++) {
        int lo = og * 8 + k;
        float a = sa[lo], d = sd[lo];
        float v0 = fmaxf(fmaf(a, acc[k][0], d), 0.f);
        float v1 = fmaxf(fmaf(a, acc[k][1], d), 0.f);
        float v2 = fmaxf(fmaf(a, acc[k][2], d), 0.f);
        float v3 = fmaxf(fmaf(a, acc[k][3], d), 0.f);
        op[(ocBase + lo) * 64] = fmaxf(fmaxf(v0, v1), fmaxf(v2, v3));
    }
}

// ---------------------------------------------------------------------------
// Kernel 3: conv3 (64->128, 8x8, pad1) + BN + ReLU + 2x2 avgpool -> [B,2048]
// Grid (B, 8): 16 ocs per block. smem:
//   input 64*10*10 (25600B) + weights [ic][oc][12] 64*16*12 (49152B) = 74752B
//   -> 2 CTAs/SM.
// 256 threads: pos = tid&15 (4x4 pooled), og = tid>>4 -> exactly 1 oc each.
// Weight reads: 2x LDS.128 + 1x LDS.32 per ic; patch via float2.
// ---------------------------------------------------------------------------
__global__ __launch_bounds__(256) void conv3_k(
    const float* __restrict__ w, const float* __restrict__ bias,
    const float* __restrict__ gam, const float* __restrict__ bet)
{
    extern __shared__ float sm[];
    float* sin_ = sm;                 // 64*10*10 = 6400 floats
    float* swt  = sm + 6400;          // [ic][oc][12] = 64*16*12 = 12288 floats
    __shared__ float sa[16], sd[16];

    const int img = blockIdx.x;
    const int ocBase = blockIdx.y * 16;
    const int tid = threadIdx.x;

    for (int i = tid; i < 6400; i += 256) sin_[i] = 0.f;
    // stage weights transposed+padded: w[ocBase+oc][ic][kk] -> swt[ic][oc][12]
    for (int i = tid; i < 16 * 64 * 9; i += 256) {
        int oc = i / 576, rem = i - oc * 576;
        int ic = rem / 9, kk = rem - ic * 9;
        swt[ic * 192 + oc * 12 + kk] = w[(size_t)(ocBase + oc) * 576 + rem];
    }
    if (tid < 16) {
        int oc = ocBase + tid;
        float a = gam[oc] * INVS;
        sa[tid] = a;
        sd[tid] = a * bias[oc] + bet[oc];
    }
    __syncthreads();

    const float* ip = g_act2 + (size_t)img * 64 * 64;
    for (int i = tid; i < 64 * 64; i += 256) {
        int c = i >> 6, y = (i >> 3) & 7, xx = i & 7;
        sin_[c * 100 + (y + 1) * 10 + (xx + 1)] = ip[i];
    }
    __syncthreads();

    const int pos = tid & 15;
    const int py = pos >> 2, px = pos & 3;
    const int og = tid >> 4;          // 0..15, 1 oc each

    float a0 = 0.f, a1 = 0.f, a2 = 0.f, a3 = 0.f;

    for (int ic = 0; ic < 64; ic++) {
        float p[4][4];
        const float* sp = sin_ + ic * 100 + (2 * py) * 10 + 2 * px;
#pragma unroll
        for (int dy = 0; dy < 4; dy++) {
            float2 v0 = *(const float2*)(sp + dy * 10);
            float2 v1 = *(const float2*)(sp + dy * 10 + 2);
            p[dy][0] = v0.x; p[dy][1] = v0.y; p[dy][2] = v1.x; p[dy][3] = v1.y;
        }

        const float* wp = swt + ic * 192 + og * 12;
        float4 w0 = *(const float4*)(wp);
        float4 w1 = *(const float4*)(wp + 4);
        float  w8 = wp[8];
        // row ky=0: w0.x w0.y w0.z ; ky=1: w0.w w1.x w1.y ; ky=2: w1.z w1.w w8
        a0 = fmaf(p[0][0], w0.x, a0);
        a1 = fmaf(p[0][1], w0.x, a1);
        a2 = fmaf(p[1][0], w0.x, a2);
        a3 = fmaf(p[1][1], w0.x, a3);
        a0 = fmaf(p[0][1], w0.y, a0);
        a1 = fmaf(p[0][2], w0.y, a1);
        a2 = fmaf(p[1][1], w0.y, a2);
        a3 = fmaf(p[1][2], w0.y, a3);
        a0 = fmaf(p[0][2], w0.z, a0);
        a1 = fmaf(p[0][3], w0.z, a1);
        a2 = fmaf(p[1][2], w0.z, a2);
        a3 = fmaf(p[1][3], w0.z, a3);

        a0 = fmaf(p[1][0], w0.w, a0);
        a1 = fmaf(p[1][1], w0.w, a1);
        a2 = fmaf(p[2][0], w0.w, a2);
        a3 = fmaf(p[2][1], w0.w, a3);
        a0 = fmaf(p[1][1], w1.x, a0);
        a1 = fmaf(p[1][2], w1.x, a1);
        a2 = fmaf(p[2][1], w1.x, a2);
        a3 = fmaf(p[2][2], w1.x, a3);
        a0 = fmaf(p[1][2], w1.y, a0);
        a1 = fmaf(p[1][3], w1.y, a1);
        a2 = fmaf(p[2][2], w1.y, a2);
        a3 = fmaf(p[2][3], w1.y, a3);

        a0 = fmaf(p[2][0], w1.z, a0);
        a1 = fmaf(p[2][1], w1.z, a1);
        a2 = fmaf(p[3][0], w1.z, a2);
        a3 = fmaf(p[3][1], w1.z, a3);
        a0 = fmaf(p[2][1], w1.w, a0);
        a1 = fmaf(p[2][2], w1.w, a1);
        a2 = fmaf(p[3][1], w1.w, a2);
        a3 = fmaf(p[3][2], w1.w, a3);
        a0 = fmaf(p[2][2], w8, a0);
        a1 = fmaf(p[2][3], w8, a1);
        a2 = fmaf(p[3][2], w8, a2);
        a3 = fmaf(p[3][3], w8, a3);
    }

    {
        float a = sa[og], d = sd[og];
        float s = fmaxf(fmaf(a, a0, d), 0.f)
                + fmaxf(fmaf(a, a1, d), 0.f)
                + fmaxf(fmaf(a, a2, d), 0.f)
                + fmaxf(fmaf(a, a3, d), 0.f);
        g_act3[(size_t)img * 2048 + (ocBase + og) * 16 + pos] = 0.25f * s;
    }
}

// ---------------------------------------------------------------------------
// Kernel 4: FC1  h512 = relu(act3[1024,2048] @ fr1_w[512,2048]^T + b)
// Tiled SGEMM: BM=64, BN=64, BK=16, 256 threads, 4x4 micro-tile.
// K-tiles stored TRANSPOSED in smem ([kk][row], stride 68 -> 272B rows,
// 16B-aligned) so the inner loop issues 2x LDS.128 instead of 8x LDS.32.
// grid (512/64, 1024/64)
// ---------------------------------------------------------------------------
__global__ __launch_bounds__(256) void fc1_k(
    const float* __restrict__ W, const float* __restrict__ bias)
{
    __shared__ float As[16 * 68];   // [kk][row], row-major, stride 68
    __shared__ float Bs[16 * 68];

    const int obase = blockIdx.x * 64;
    const int nbase = blockIdx.y * 64;
    const int tid = threadIdx.x;
    const int ty = tid >> 4, tx = tid & 15;

    const int lr = tid >> 2;          // row 0..63
    const int lc = (tid & 3) * 4;     // k-col 0,4,8,12

    float acc[4][4];
#pragma unroll
    for (int i = 0; i < 4; i++)
#pragma unroll
        for (int j = 0; j < 4; j++) acc[i][j] = 0.f;

    for (int k0 = 0; k0 < 2048; k0 += 16) {
        float4 av = *(const float4*)(g_act3 + (size_t)(nbase + lr) * 2048 + k0 + lc);
        float4 bv = *(const float4*)(W + (size_t)(obase + lr) * 2048 + k0 + lc);
        As[(lc + 0) * 68 + lr] = av.x;
        As[(lc + 1) * 68 + lr] = av.y;
        As[(lc + 2) * 68 + lr] = av.z;
        As[(lc + 3) * 68 + lr] = av.w;
        Bs[(lc + 0) * 68 + lr] = bv.x;
        Bs[(lc + 1) * 68 + lr] = bv.y;
        Bs[(lc + 2) * 68 + lr] = bv.z;
        Bs[(lc + 3) * 68 + lr] = bv.w;
        __syncthreads();
#pragma unroll
        for (int kk = 0; kk < 16; kk++) {
            float4 a = *(const float4*)&As[kk * 68 + ty * 4];
            float4 b = *(const float4*)&Bs[kk * 68 + tx * 4];
            acc[0][0] = fmaf(a.x, b.x, acc[0][0]);
            acc[0][1] = fmaf(a.x, b.y, acc[0][1]);
            acc[0][2] = fmaf(a.x, b.z, acc[0][2]);
            acc[0][3] = fmaf(a.x, b.w, acc[0][3]);
            acc[1][0] = fmaf(a.y, b.x, acc[1][0]);
            acc[1][1] = fmaf(a.y, b.y, acc[1][1]);
            acc[1][2] = fmaf(a.y, b.z, acc[1][2]);
            acc[1][3] = fmaf(a.y, b.w, acc[1][3]);
            acc[2][0] = fmaf(a.z, b.x, acc[2][0]);
            acc[2][1] = fmaf(a.z, b.y, acc[2][1]);
            acc[2][2] = fmaf(a.z, b.z, acc[2][2]);
            acc[2][3] = fmaf(a.z, b.w, acc[2][3]);
            acc[3][0] = fmaf(a.w, b.x, acc[3][0]);
            acc[3][1] = fmaf(a.w, b.y, acc[3][1]);
            acc[3][2] = fmaf(a.w, b.z, acc[3][2]);
            acc[3][3] = fmaf(a.w, b.w, acc[3][3]);
        }
        __syncthreads();
    }

#pragma unroll
    for (int i = 0; i < 4; i++) {
        int n = nbase + ty * 4 + i;
#pragma unroll
        for (int j = 0; j < 4; j++) {
            int o = obase + tx * 4 + j;
            g_h512[(size_t)n * 512 + o] = fmaxf(acc[i][j] + bias[o], 0.f);
        }
    }
}

// ---------------------------------------------------------------------------
// Kernel 5: build total 16x16 complex unitary from q_weights.
// U_l = CNOT_RING @ kron_q RX(theta_lq);  Utot = U_2 @ U_1  (psi' = Utot psi).
// One block, 256 threads (one per matrix element).
// ---------------------------------------------------------------------------
__global__ void qprep_k(const float* __restrict__ qw)
{
    __shared__ float2 U1[256], U2[256];
    const int tid = threadIdx.x;
    const int i = tid >> 4, j = tid & 15;

    for (int l = 0; l < 2; l++) {
        float re = 1.f, im = 0.f;
#pragma unroll
        for (int q = 0; q < 4; q++) {
            float th = qw[l * 4 + q] * 0.5f;
            float c = cosf(th), s = sinf(th);
            int bi = (i >> (3 - q)) & 1, bj = (j >> (3 - q)) & 1;
            if (bi == bj) { re *= c; im *= c; }
            else { float nr = im * s, ni = -re * s; re = nr; im = ni; }  // *(0,-s)
        }
        // CNOT ring permutation of row index i (wire w -> bit (3-w))
        int bb = i;
        if ((bb >> 3) & 1) bb ^= 4;   // CNOT(0,1)
        if ((bb >> 2) & 1) bb ^= 2;   // CNOT(1,2)
        if ((bb >> 1) & 1) bb ^= 1;   // CNOT(2,3)
        if (bb & 1)        bb ^= 8;   // CNOT(3,0)
        float2 v = make_float2(re, im);
        if (l == 0) U1[bb * 16 + j] = v; else U2[bb * 16 + j] = v;
    }
    __syncthreads();

    float ar = 0.f, ai = 0.f;
#pragma unroll
    for (int k = 0; k < 16; k++) {
        float2 a = U2[i * 16 + k], b = U1[k * 16 + j];
        ar += a.x * b.x - a.y * b.y;
        ai += a.x * b.y + a.y * b.x;
    }
    g_Utot[tid] = make_float2(ar, ai);
}

// ---------------------------------------------------------------------------
// Kernel 6: fused tail per sample:
//   FC2 (512->16) -> softmax -> L2-normalize -> psi' = Utot psi -> |psi'|^2
//   -> Z expvals (4) -> head: 4->128 (BN eval + ReLU) -> 128->100
// grid B, 128 threads.
// ---------------------------------------------------------------------------
__global__ __launch_bounds__(128) void tail_k(
    const float* __restrict__ fr2w, const float* __restrict__ fr2b,
    const float* __restrict__ h1w,  const float* __restrict__ h1b,
    const float* __restrict__ bnhg, const float* __restrict__ bnhb,
    const float* __restrict__ h2w,  const float* __restrict__ h2b,
    float* __restrict__ out)
{
    __shared__ float sh[512];
    __shared__ float2 sU[256];
    __shared__ float logits[16];
    __shared__ float psi[16];
    __shared__ float probs[16];
    __shared__ float qv[4];
    __shared__ float t1[128];

    const int bimg = blockIdx.x;
    const int tid = threadIdx.x;

    const float* hp = g_h512 + (size_t)bimg * 512;
    for (int i = tid; i < 512; i += 128) sh[i] = hp[i];
    sU[tid] = g_Utot[tid];
    sU[tid + 128] = g_Utot[tid + 128];
    __syncthreads();

    // FC2: 16 outputs x 8-thread partial sums
    {
        int o = tid >> 3, c = tid & 7;
        const float* wr = fr2w + (size_t)o * 512 + c * 64;
        const float* hr = sh + c * 64;
        float s = 0.f;
#pragma unroll 8
        for (int k = 0; k < 64; k++) s = fmaf(hr[k], wr[k], s);
        s += __shfl_xor_sync(0xffffffffu, s, 4, 8);
        s += __shfl_xor_sync(0xffffffffu, s, 2, 8);
        s += __shfl_xor_sync(0xffffffffu, s, 1, 8);
        if (c == 0) logits[o] = s + fr2b[o];
    }
    __syncthreads();

    // softmax + L2 normalization (lanes 0..15 of warp 0)
    if (tid < 16) {
        float v = logits[tid];
        float m = v;
#pragma unroll
        for (int off = 8; off > 0; off >>= 1)
            m = fmaxf(m, __shfl_xor_sync(0x0000ffffu, m, off, 16));
        float e = expf(v - m);
        float sum = e;
#pragma unroll
        for (int off = 8; off > 0; off >>= 1)
            sum += __shfl_xor_sync(0x0000ffffu, sum, off, 16);
        float f = e / sum;
        float s2 = f * f;
#pragma unroll
        for (int off = 8; off > 0; off >>= 1)
            s2 += __shfl_xor_sync(0x0000ffffu, s2, off, 16);
        psi[tid] = f / sqrtf(s2);
    }
    __syncthreads();

    // apply Utot, probabilities
    if (tid < 16) {
        float yr = 0.f, yi = 0.f;
#pragma unroll
        for (int jj = 0; jj < 16; jj++) {
            float2 u = sU[tid * 16 + jj];
            float p = psi[jj];
            yr = fmaf(u.x, p, yr);
            yi = fmaf(u.y, p, yi);
        }
        probs[tid] = yr * yr + yi * yi;
    }
    __syncthreads();

    // Pauli-Z expectation values
    if (tid < 4) {
        float e = 0.f;
#pragma unroll
        for (int bb = 0; bb < 16; bb++) {
            float z = 1.f - 2.f * (float)((bb >> (3 - tid)) & 1);
            e = fmaf(probs[bb], z, e);
        }
        qv[tid] = e;
    }
    __syncthreads();

    // head layer 1: 4 -> 128 with eval-mode BN + ReLU
    {
        float v = h1b[tid];
#pragma unroll
        for (int k = 0; k < 4; k++) v = fmaf(h1w[tid * 4 + k], qv[k], v);
        v = fmaf(bnhg[tid] * INVS, v, bnhb[tid]);
        t1[tid] = fmaxf(v, 0.f);
    }
    __syncthreads();

    // head layer 2: 128 -> 100
    if (tid < 100) {
        const float* wr = h2w + (size_t)tid * 128;
        float s = h2b[tid];
#pragma unroll 8
        for (int jj = 0; jj < 128; jj++) s = fmaf(t1[jj], wr[jj], s);
        out[(size_t)bimg * 100 + tid] = s;
    }
}

// ---------------------------------------------------------------------------
// Launch
// ---------------------------------------------------------------------------
extern "C" void kernel_launch(void* const* d_in, const int* in_sizes, int n_in,
                              void* d_out, int out_size)
{
    const float* x       = (const float*)d_in[0];
    const float* conv1_w = (const float*)d_in[1];
    const float* conv1_b = (const float*)d_in[2];
    const float* bn1_g   = (const float*)d_in[3];
    const float* bn1_b   = (const float*)d_in[4];
    const float* conv2_w = (const float*)d_in[5];
    const float* conv2_b = (const float*)d_in[6];
    const float* bn2_g   = (const float*)d_in[7];
    const float* bn2_b   = (const float*)d_in[8];
    const float* conv3_w = (const float*)d_in[9];
    const float* conv3_b = (const float*)d_in[10];
    const float* bn3_g   = (const float*)d_in[11];
    const float* bn3_b   = (const float*)d_in[12];
    const float* fr1_w   = (const float*)d_in[13];
    const float* fr1_b   = (const float*)d_in[14];
    const float* fr2_w   = (const float*)d_in[15];
    const float* fr2_b   = (const float*)d_in[16];
    const float* q_w     = (const float*)d_in[17];
    const float* h1_w    = (const float*)d_in[18];
    const float* h1_b    = (const float*)d_in[19];
    const float* bnh_g   = (const float*)d_in[20];
    const float* bnh_b   = (const float*)d_in[21];
    const float* h2_w    = (const float*)d_in[22];
    const float* h2_b    = (const float*)d_in[23];
    float* out = (float*)d_out;

    // Idempotent, host-side, capture-safe. No static guards (harness rule).
    cudaFuncSetAttribute(conv2_k, cudaFuncAttributeMaxDynamicSharedMemorySize, 90624);
    cudaFuncSetAttribute(conv3_k, cudaFuncAttributeMaxDynamicSharedMemorySize, 74752);

    conv1_k<<<B, 256>>>(x, conv1_w, conv1_b, bn1_g, bn1_b);
    conv2_k<<<dim3(B, 2), 256, 90624>>>(conv2_w, conv2_b, bn2_g, bn2_b);
    conv3_k<<<dim3(B, 8), 256, 74752>>>(conv3_w, conv3_b, bn3_g, bn3_b);
    fc1_k<<<dim3(512 / 64, B / 64), 256>>>(fr1_w, fr1_b);
    qprep_k<<<1, 256>>>(q_w);
    tail_k<<<B, 128>>>(fr2_w, fr2_b, h1_w, h1_b, bnh_g, bnh_b, h2_w, h2_b, out);
}

// round 8
// speedup vs baseline: 1.0185x; 1.0185x over previous
#include <cuda_runtime.h>
#include <cuda_bf16.h>
#include <math.h>

// ---------------------------------------------------------------------------
// EnhancedHybridModel: conv stack -> FC -> 4-qubit sim -> head.  B = 1024.
// ---------------------------------------------------------------------------

#define B 1024
#define INVS 0.99999500003749968f   // 1/sqrt(1+1e-5)

__device__ float g_act1[B * 32 * 16 * 16];   // after conv1+pool
__device__ float g_act2[B * 64 * 8 * 8];     // after conv2+pool
__device__ float g_act3[B * 2048];           // after conv3+avgpool
__device__ float g_fc1p[4 * B * 512];        // fc1 split-K partials (8MB)
__device__ float g_h512[B * 512];            // after FC1+ReLU
__device__ float2 g_Utot[16 * 16];           // total quantum unitary

// ---------------------------------------------------------------------------
// Kernel 1: conv1 (3->32, 32x32, pad1) + BN + ReLU + 2x2 maxpool -> [B,32,16,16]
// ---------------------------------------------------------------------------
__global__ __launch_bounds__(256) void conv1_k(
    const float* __restrict__ x, const float* __restrict__ w,
    const float* __restrict__ bias, const float* __restrict__ gam,
    const float* __restrict__ bet)
{
    __shared__ float sin_[3 * 34 * 34];
    __shared__ float sw_[32 * 27];
    __shared__ float sa[32], sd[32];

    const int img = blockIdx.x;
    const int tid = threadIdx.x;

    for (int i = tid; i < 3 * 34 * 34; i += 256) sin_[i] = 0.f;
    if (tid < 216) ((float4*)sw_)[tid] = ((const float4*)w)[tid];
    if (tid < 32) {
        float a = gam[tid] * INVS;
        sa[tid] = a;
        sd[tid] = a * bias[tid] + bet[tid];
    }
    __syncthreads();

    const float* xp = x + (size_t)img * 3 * 32 * 32;
    for (int i = tid; i < 3 * 32 * 32; i += 256) {
        int c = i >> 10, y = (i >> 5) & 31, xx = i & 31;
        sin_[c * (34 * 34) + (y + 1) * 34 + (xx + 1)] = xp[i];
    }
    __syncthreads();

    const int py = tid >> 4, px = tid & 15;

    float patch[3][4][4];
#pragma unroll
    for (int c = 0; c < 3; c++)
#pragma unroll
        for (int dy = 0; dy < 4; dy++)
#pragma unroll
            for (int dx = 0; dx < 4; dx++)
                patch[c][dy][dx] = sin_[c * (34 * 34) + (2 * py + dy) * 34 + (2 * px + dx)];

    float* op = g_act1 + (size_t)img * 32 * 256 + py * 16 + px;

    for (int oc = 0; oc < 32; oc++) {
        float a0 = 0.f, a1 = 0.f, a2 = 0.f, a3 = 0.f;
        const float* wk = sw_ + oc * 27;
#pragma unroll
        for (int c = 0; c < 3; c++)
#pragma unroll
            for (int ky = 0; ky < 3; ky++)
#pragma unroll
                for (int kx = 0; kx < 3; kx++) {
                    float wv = wk[c * 9 + ky * 3 + kx];
                    a0 = fmaf(patch[c][ky][kx],         wv, a0);
                    a1 = fmaf(patch[c][ky][kx + 1],     wv, a1);
                    a2 = fmaf(patch[c][ky + 1][kx],     wv, a2);
                    a3 = fmaf(patch[c][ky + 1][kx + 1], wv, a3);
                }
        float a = sa[oc], d = sd[oc];
        float v0 = fmaxf(fmaf(a, a0, d), 0.f);
        float v1 = fmaxf(fmaf(a, a1, d), 0.f);
        float v2 = fmaxf(fmaf(a, a2, d), 0.f);
        float v3 = fmaxf(fmaf(a, a3, d), 0.f);
        op[oc * 256] = fmaxf(fmaxf(v0, v1), fmaxf(v2, v3));
    }
}

// ---------------------------------------------------------------------------
// Kernel 2: conv2 (32->64, 16x16, pad1) + BN + ReLU + maxpool -> [B,64,8,8]
// Grid (B, 4): 16 ocs/block. smem: input 41472B + weights [ic][16][12] 24576B
// = 66048B -> 3 CTAs/SM (24 warps).
// 256 threads: pos = tid&63 (8x8 pooled), og = tid>>6 -> 4 ocs each.
// ---------------------------------------------------------------------------
__global__ __launch_bounds__(256) void conv2_k(
    const float* __restrict__ w, const float* __restrict__ bias,
    const float* __restrict__ gam, const float* __restrict__ bet)
{
    extern __shared__ float sm[];
    float* sin_ = sm;                 // 32*18*18 = 10368 floats
    float* swt  = sm + 10368;         // [ic][oc][12] = 32*16*12 = 6144 floats
    __shared__ float sa[16], sd[16];

    const int img = blockIdx.x;
    const int ocBase = blockIdx.y * 16;
    const int tid = threadIdx.x;

    for (int i = tid; i < 10368; i += 256) sin_[i] = 0.f;
    for (int i = tid; i < 16 * 32 * 9; i += 256) {
        int oc = i / 288, rem = i - oc * 288;
        int ic = rem / 9, kk = rem - ic * 9;
        swt[ic * 192 + oc * 12 + kk] = w[(size_t)(ocBase + oc) * 288 + rem];
    }
    if (tid < 16) {
        int oc = ocBase + tid;
        float a = gam[oc] * INVS;
        sa[tid] = a;
        sd[tid] = a * bias[oc] + bet[oc];
    }
    __syncthreads();

    const float* ip = g_act1 + (size_t)img * 32 * 256;
    for (int i = tid; i < 32 * 256; i += 256) {
        int c = i >> 8, y = (i >> 4) & 15, xx = i & 15;
        sin_[c * 324 + (y + 1) * 18 + (xx + 1)] = ip[i];
    }
    __syncthreads();

    const int pos = tid & 63;
    const int py = pos >> 3, px = pos & 7;
    const int og = tid >> 6;          // 0..3, 4 ocs each

    float acc[4][4];
#pragma unroll
    for (int k = 0; k < 4; k++)
#pragma unroll
        for (int p = 0; p < 4; p++) acc[k][p] = 0.f;

    for (int ic = 0; ic < 32; ic++) {
        float p[4][4];
        const float* sp = sin_ + ic * 324 + (2 * py) * 18 + 2 * px;
#pragma unroll
        for (int dy = 0; dy < 4; dy++) {
            float2 v0 = *(const float2*)(sp + dy * 18);
            float2 v1 = *(const float2*)(sp + dy * 18 + 2);
            p[dy][0] = v0.x; p[dy][1] = v0.y; p[dy][2] = v1.x; p[dy][3] = v1.y;
        }

        const float* wp = swt + ic * 192 + (og * 4) * 12;
#pragma unroll
        for (int k = 0; k < 4; k++) {
            float4 w0 = *(const float4*)(wp + k * 12);
            float4 w1 = *(const float4*)(wp + k * 12 + 4);
            float  w8 = wp[k * 12 + 8];
            // row ky=0: w0.x w0.y w0.z ; ky=1: w0.w w1.x w1.y ; ky=2: w1.z w1.w w8
            acc[k][0] = fmaf(p[0][0], w0.x, acc[k][0]);
            acc[k][1] = fmaf(p[0][1], w0.x, acc[k][1]);
            acc[k][2] = fmaf(p[1][0], w0.x, acc[k][2]);
            acc[k][3] = fmaf(p[1][1], w0.x, acc[k][3]);
            acc[k][0] = fmaf(p[0][1], w0.y, acc[k][0]);
            acc[k][1] = fmaf(p[0][2], w0.y, acc[k][1]);
            acc[k][2] = fmaf(p[1][1], w0.y, acc[k][2]);
            acc[k][3] = fmaf(p[1][2], w0.y, acc[k][3]);
            acc[k][0] = fmaf(p[0][2], w0.z, acc[k][0]);
            acc[k][1] = fmaf(p[0][3], w0.z, acc[k][1]);
            acc[k][2] = fmaf(p[1][2], w0.z, acc[k][2]);
            acc[k][3] = fmaf(p[1][3], w0.z, acc[k][3]);

            acc[k][0] = fmaf(p[1][0], w0.w, acc[k][0]);
            acc[k][1] = fmaf(p[1][1], w0.w, acc[k][1]);
            acc[k][2] = fmaf(p[2][0], w0.w, acc[k][2]);
            acc[k][3] = fmaf(p[2][1], w0.w, acc[k][3]);
            acc[k][0] = fmaf(p[1][1], w1.x, acc[k][0]);
            acc[k][1] = fmaf(p[1][2], w1.x, acc[k][1]);
            acc[k][2] = fmaf(p[2][1], w1.x, acc[k][2]);
            acc[k][3] = fmaf(p[2][2], w1.x, acc[k][3]);
            acc[k][0] = fmaf(p[1][2], w1.y, acc[k][0]);
            acc[k][1] = fmaf(p[1][3], w1.y, acc[k][1]);
            acc[k][2] = fmaf(p[2][2], w1.y, acc[k][2]);
            acc[k][3] = fmaf(p[2][3], w1.y, acc[k][3]);

            acc[k][0] = fmaf(p[2][0], w1.z, acc[k][0]);
            acc[k][1] = fmaf(p[2][1], w1.z, acc[k][1]);
            acc[k][2] = fmaf(p[3][0], w1.z, acc[k][2]);
            acc[k][3] = fmaf(p[3][1], w1.z, acc[k][3]);
            acc[k][0] = fmaf(p[2][1], w1.w, acc[k][0]);
            acc[k][1] = fmaf(p[2][2], w1.w, acc[k][1]);
            acc[k][2] = fmaf(p[3][1], w1.w, acc[k][2]);
            acc[k][3] = fmaf(p[3][2], w1.w, acc[k][3]);
            acc[k][0] = fmaf(p[2][2], w8, acc[k][0]);
            acc[k][1] = fmaf(p[2][3], w8, acc[k][1]);
            acc[k][2] = fmaf(p[3][2], w8, acc[k][2]);
            acc[k][3] = fmaf(p[3][3], w8, acc[k][3]);
        }
    }

    float* op = g_act2 + (size_t)img * 64 * 64 + pos;
#pragma unroll
    for (int k = 0; k < 4; k++) {
        int lo = og * 4 + k;
        float a = sa[lo], d = sd[lo];
        float v0 = fmaxf(fmaf(a, acc[k][0], d), 0.f);
        float v1 = fmaxf(fmaf(a, acc[k][1], d), 0.f);
        float v2 = fmaxf(fmaf(a, acc[k][2], d), 0.f);
        float v3 = fmaxf(fmaf(a, acc[k][3], d), 0.f);
        op[(ocBase + lo) * 64] = fmaxf(fmaxf(v0, v1), fmaxf(v2, v3));
    }
}

// ---------------------------------------------------------------------------
// Kernel 3: conv3 (64->128, 8x8, pad1) + BN + ReLU + 2x2 avgpool -> [B,2048]
// Grid (B, 8): 16 ocs/block, 1 oc per thread-group. smem 74752B.
// ---------------------------------------------------------------------------
__global__ __launch_bounds__(256) void conv3_k(
    const float* __restrict__ w, const float* __restrict__ bias,
    const float* __restrict__ gam, const float* __restrict__ bet)
{
    extern __shared__ float sm[];
    float* sin_ = sm;                 // 64*10*10 = 6400 floats
    float* swt  = sm + 6400;          // [ic][oc][12] = 64*16*12 = 12288 floats
    __shared__ float sa[16], sd[16];

    const int img = blockIdx.x;
    const int ocBase = blockIdx.y * 16;
    const int tid = threadIdx.x;

    for (int i = tid; i < 6400; i += 256) sin_[i] = 0.f;
    for (int i = tid; i < 16 * 64 * 9; i += 256) {
        int oc = i / 576, rem = i - oc * 576;
        int ic = rem / 9, kk = rem - ic * 9;
        swt[ic * 192 + oc * 12 + kk] = w[(size_t)(ocBase + oc) * 576 + rem];
    }
    if (tid < 16) {
        int oc = ocBase + tid;
        float a = gam[oc] * INVS;
        sa[tid] = a;
        sd[tid] = a * bias[oc] + bet[oc];
    }
    __syncthreads();

    const float* ip = g_act2 + (size_t)img * 64 * 64;
    for (int i = tid; i < 64 * 64; i += 256) {
        int c = i >> 6, y = (i >> 3) & 7, xx = i & 7;
        sin_[c * 100 + (y + 1) * 10 + (xx + 1)] = ip[i];
    }
    __syncthreads();

    const int pos = tid & 15;
    const int py = pos >> 2, px = pos & 3;
    const int og = tid >> 4;          // 0..15, 1 oc each

    float a0 = 0.f, a1 = 0.f, a2 = 0.f, a3 = 0.f;

    for (int ic = 0; ic < 64; ic++) {
        float p[4][4];
        const float* sp = sin_ + ic * 100 + (2 * py) * 10 + 2 * px;
#pragma unroll
        for (int dy = 0; dy < 4; dy++) {
            float2 v0 = *(const float2*)(sp + dy * 10);
            float2 v1 = *(const float2*)(sp + dy * 10 + 2);
            p[dy][0] = v0.x; p[dy][1] = v0.y; p[dy][2] = v1.x; p[dy][3] = v1.y;
        }

        const float* wp = swt + ic * 192 + og * 12;
        float4 w0 = *(const float4*)(wp);
        float4 w1 = *(const float4*)(wp + 4);
        float  w8 = wp[8];
        a0 = fmaf(p[0][0], w0.x, a0);
        a1 = fmaf(p[0][1], w0.x, a1);
        a2 = fmaf(p[1][0], w0.x, a2);
        a3 = fmaf(p[1][1], w0.x, a3);
        a0 = fmaf(p[0][1], w0.y, a0);
        a1 = fmaf(p[0][2], w0.y, a1);
        a2 = fmaf(p[1][1], w0.y, a2);
        a3 = fmaf(p[1][2], w0.y, a3);
        a0 = fmaf(p[0][2], w0.z, a0);
        a1 = fmaf(p[0][3], w0.z, a1);
        a2 = fmaf(p[1][2], w0.z, a2);
        a3 = fmaf(p[1][3], w0.z, a3);

        a0 = fmaf(p[1][0], w0.w, a0);
        a1 = fmaf(p[1][1], w0.w, a1);
        a2 = fmaf(p[2][0], w0.w, a2);
        a3 = fmaf(p[2][1], w0.w, a3);
        a0 = fmaf(p[1][1], w1.x, a0);
        a1 = fmaf(p[1][2], w1.x, a1);
        a2 = fmaf(p[2][1], w1.x, a2);
        a3 = fmaf(p[2][2], w1.x, a3);
        a0 = fmaf(p[1][2], w1.y, a0);
        a1 = fmaf(p[1][3], w1.y, a1);
        a2 = fmaf(p[2][2], w1.y, a2);
        a3 = fmaf(p[2][3], w1.y, a3);

        a0 = fmaf(p[2][0], w1.z, a0);
        a1 = fmaf(p[2][1], w1.z, a1);
        a2 = fmaf(p[3][0], w1.z, a2);
        a3 = fmaf(p[3][1], w1.z, a3);
        a0 = fmaf(p[2][1], w1.w, a0);
        a1 = fmaf(p[2][2], w1.w, a1);
        a2 = fmaf(p[3][1], w1.w, a2);
        a3 = fmaf(p[3][2], w1.w, a3);
        a0 = fmaf(p[2][2], w8, a0);
        a1 = fmaf(p[2][3], w8, a1);
        a2 = fmaf(p[3][2], w8, a2);
        a3 = fmaf(p[3][3], w8, a3);
    }

    {
        float a = sa[og], d = sd[og];
        float s = fmaxf(fmaf(a, a0, d), 0.f)
                + fmaxf(fmaf(a, a1, d), 0.f)
                + fmaxf(fmaf(a, a2, d), 0.f)
                + fmaxf(fmaf(a, a3, d), 0.f);
        g_act3[(size_t)img * 2048 + (ocBase + og) * 16 + pos] = 0.25f * s;
    }
}

// ---------------------------------------------------------------------------
// Kernel 4a: FC1 split-K partial.  grid (8, 16, 4): 512 CTAs.
// Each CTA: 64x64 tile over K-chunk of 512. Writes raw partial sums.
// ---------------------------------------------------------------------------
__global__ __launch_bounds__(256) void fc1_k(const float* __restrict__ W)
{
    __shared__ float As[16 * 68];   // [kk][row], stride 68
    __shared__ float Bs[16 * 68];

    const int obase = blockIdx.x * 64;
    const int nbase = blockIdx.y * 64;
    const int kz    = blockIdx.z;         // 0..3, K-chunk of 512
    const int tid = threadIdx.x;
    const int ty = tid >> 4, tx = tid & 15;

    const int lr = tid >> 2;          // row 0..63
    const int lc = (tid & 3) * 4;     // k-col 0,4,8,12

    float acc[4][4];
#pragma unroll
    for (int i = 0; i < 4; i++)
#pragma unroll
        for (int j = 0; j < 4; j++) acc[i][j] = 0.f;

    const int kbeg = kz * 512, kend = kbeg + 512;
    for (int k0 = kbeg; k0 < kend; k0 += 16) {
        float4 av = *(const float4*)(g_act3 + (size_t)(nbase + lr) * 2048 + k0 + lc);
        float4 bv = *(const float4*)(W + (size_t)(obase + lr) * 2048 + k0 + lc);
        As[(lc + 0) * 68 + lr] = av.x;
        As[(lc + 1) * 68 + lr] = av.y;
        As[(lc + 2) * 68 + lr] = av.z;
        As[(lc + 3) * 68 + lr] = av.w;
        Bs[(lc + 0) * 68 + lr] = bv.x;
        Bs[(lc + 1) * 68 + lr] = bv.y;
        Bs[(lc + 2) * 68 + lr] = bv.z;
        Bs[(lc + 3) * 68 + lr] = bv.w;
        __syncthreads();
#pragma unroll
        for (int kk = 0; kk < 16; kk++) {
            float4 a = *(const float4*)&As[kk * 68 + ty * 4];
            float4 b = *(const float4*)&Bs[kk * 68 + tx * 4];
            acc[0][0] = fmaf(a.x, b.x, acc[0][0]);
            acc[0][1] = fmaf(a.x, b.y, acc[0][1]);
            acc[0][2] = fmaf(a.x, b.z, acc[0][2]);
            acc[0][3] = fmaf(a.x, b.w, acc[0][3]);
            acc[1][0] = fmaf(a.y, b.x, acc[1][0]);
            acc[1][1] = fmaf(a.y, b.y, acc[1][1]);
            acc[1][2] = fmaf(a.y, b.z, acc[1][2]);
            acc[1][3] = fmaf(a.y, b.w, acc[1][3]);
            acc[2][0] = fmaf(a.z, b.x, acc[2][0]);
            acc[2][1] = fmaf(a.z, b.y, acc[2][1]);
            acc[2][2] = fmaf(a.z, b.z, acc[2][2]);
            acc[2][3] = fmaf(a.z, b.w, acc[2][3]);
            acc[3][0] = fmaf(a.w, b.x, acc[3][0]);
            acc[3][1] = fmaf(a.w, b.y, acc[3][1]);
            acc[3][2] = fmaf(a.w, b.z, acc[3][2]);
            acc[3][3] = fmaf(a.w, b.w, acc[3][3]);
        }
        __syncthreads();
    }

    float* pp = g_fc1p + (size_t)kz * B * 512;
#pragma unroll
    for (int i = 0; i < 4; i++) {
        int n = nbase + ty * 4 + i;
#pragma unroll
        for (int j = 0; j < 4; j++) {
            int o = obase + tx * 4 + j;
            pp[(size_t)n * 512 + o] = acc[i][j];
        }
    }
}

// ---------------------------------------------------------------------------
// Kernel 4b: FC1 reduce: sum 4 partials + bias + ReLU -> g_h512.
// grid 512, 256 threads, float4 per thread.
// ---------------------------------------------------------------------------
__global__ __launch_bounds__(256) void fc1_red(const float* __restrict__ bias)
{
    const int idx = blockIdx.x * 256 + threadIdx.x;   // float4 index
    const int e0 = idx * 4;
    const int o = e0 & 511;

    float4 s0 = *(const float4*)(g_fc1p + e0);
    float4 s1 = *(const float4*)(g_fc1p + (size_t)B * 512 + e0);
    float4 s2 = *(const float4*)(g_fc1p + (size_t)2 * B * 512 + e0);
    float4 s3 = *(const float4*)(g_fc1p + (size_t)3 * B * 512 + e0);
    float4 bv = *(const float4*)(bias + o);

    float4 r;
    r.x = fmaxf(s0.x + s1.x + s2.x + s3.x + bv.x, 0.f);
    r.y = fmaxf(s0.y + s1.y + s2.y + s3.y + bv.y, 0.f);
    r.z = fmaxf(s0.z + s1.z + s2.z + s3.z + bv.z, 0.f);
    r.w = fmaxf(s0.w + s1.w + s2.w + s3.w + bv.w, 0.f);
    *(float4*)(g_h512 + e0) = r;
}

// ---------------------------------------------------------------------------
// Kernel 5: build total 16x16 complex unitary from q_weights.
// ---------------------------------------------------------------------------
__global__ void qprep_k(const float* __restrict__ qw)
{
    __shared__ float2 U1[256], U2[256];
    const int tid = threadIdx.x;
    const int i = tid >> 4, j = tid & 15;

    for (int l = 0; l < 2; l++) {
        float re = 1.f, im = 0.f;
#pragma unroll
        for (int q = 0; q < 4; q++) {
            float th = qw[l * 4 + q] * 0.5f;
            float c = cosf(th), s = sinf(th);
            int bi = (i >> (3 - q)) & 1, bj = (j >> (3 - q)) & 1;
            if (bi == bj) { re *= c; im *= c; }
            else { float nr = im * s, ni = -re * s; re = nr; im = ni; }
        }
        int bb = i;
        if ((bb >> 3) & 1) bb ^= 4;
        if ((bb >> 2) & 1) bb ^= 2;
        if ((bb >> 1) & 1) bb ^= 1;
        if (bb & 1)        bb ^= 8;
        float2 v = make_float2(re, im);
        if (l == 0) U1[bb * 16 + j] = v; else U2[bb * 16 + j] = v;
    }
    __syncthreads();

    float ar = 0.f, ai = 0.f;
#pragma unroll
    for (int k = 0; k < 16; k++) {
        float2 a = U2[i * 16 + k], b = U1[k * 16 + j];
        ar += a.x * b.x - a.y * b.y;
        ai += a.x * b.y + a.y * b.x;
    }
    g_Utot[tid] = make_float2(ar, ai);
}

// ---------------------------------------------------------------------------
// Kernel 6: fused tail per sample. grid B, 128 threads.
// ---------------------------------------------------------------------------
__global__ __launch_bounds__(128) void tail_k(
    const float* __restrict__ fr2w, const float* __restrict__ fr2b,
    const float* __restrict__ h1w,  const float* __restrict__ h1b,
    const float* __restrict__ bnhg, const float* __restrict__ bnhb,
    const float* __restrict__ h2w,  const float* __restrict__ h2b,
    float* __restrict__ out)
{
    __shared__ float sh[512];
    __shared__ float2 sU[256];
    __shared__ float logits[16];
    __shared__ float psi[16];
    __shared__ float probs[16];
    __shared__ float qv[4];
    __shared__ float t1[128];

    const int bimg = blockIdx.x;
    const int tid = threadIdx.x;

    const float* hp = g_h512 + (size_t)bimg * 512;
    for (int i = tid; i < 512; i += 128) sh[i] = hp[i];
    sU[tid] = g_Utot[tid];
    sU[tid + 128] = g_Utot[tid + 128];
    __syncthreads();

    {
        int o = tid >> 3, c = tid & 7;
        const float* wr = fr2w + (size_t)o * 512 + c * 64;
        const float* hr = sh + c * 64;
        float s = 0.f;
#pragma unroll 8
        for (int k = 0; k < 64; k++) s = fmaf(hr[k], wr[k], s);
        s += __shfl_xor_sync(0xffffffffu, s, 4, 8);
        s += __shfl_xor_sync(0xffffffffu, s, 2, 8);
        s += __shfl_xor_sync(0xffffffffu, s, 1, 8);
        if (c == 0) logits[o] = s + fr2b[o];
    }
    __syncthreads();

    if (tid < 16) {
        float v = logits[tid];
        float m = v;
#pragma unroll
        for (int off = 8; off > 0; off >>= 1)
            m = fmaxf(m, __shfl_xor_sync(0x0000ffffu, m, off, 16));
        float e = expf(v - m);
        float sum = e;
#pragma unroll
        for (int off = 8; off > 0; off >>= 1)
            sum += __shfl_xor_sync(0x0000ffffu, sum, off, 16);
        float f = e / sum;
        float s2 = f * f;
#pragma unroll
        for (int off = 8; off > 0; off >>= 1)
            s2 += __shfl_xor_sync(0x0000ffffu, s2, off, 16);
        psi[tid] = f / sqrtf(s2);
    }
    __syncthreads();

    if (tid < 16) {
        float yr = 0.f, yi = 0.f;
#pragma unroll
        for (int jj = 0; jj < 16; jj++) {
            float2 u = sU[tid * 16 + jj];
            float p = psi[jj];
            yr = fmaf(u.x, p, yr);
            yi = fmaf(u.y, p, yi);
        }
        probs[tid] = yr * yr + yi * yi;
    }
    __syncthreads();

    if (tid < 4) {
        float e = 0.f;
#pragma unroll
        for (int bb = 0; bb < 16; bb++) {
            float z = 1.f - 2.f * (float)((bb >> (3 - tid)) & 1);
            e = fmaf(probs[bb], z, e);
        }
        qv[tid] = e;
    }
    __syncthreads();

    {
        float v = h1b[tid];
#pragma unroll
        for (int k = 0; k < 4; k++) v = fmaf(h1w[tid * 4 + k], qv[k], v);
        v = fmaf(bnhg[tid] * INVS, v, bnhb[tid]);
        t1[tid] = fmaxf(v, 0.f);
    }
    __syncthreads();

    if (tid < 100) {
        const float* wr = h2w + (size_t)tid * 128;
        float s = h2b[tid];
#pragma unroll 8
        for (int jj = 0; jj < 128; jj++) s = fmaf(t1[jj], wr[jj], s);
        out[(size_t)bimg * 100 + tid] = s;
    }
}

// ---------------------------------------------------------------------------
// Launch
// ---------------------------------------------------------------------------
extern "C" void kernel_launch(void* const* d_in, const int* in_sizes, int n_in,
                              void* d_out, int out_size)
{
    const float* x       = (const float*)d_in[0];
    const float* conv1_w = (const float*)d_in[1];
    const float* conv1_b = (const float*)d_in[2];
    const float* bn1_g   = (const float*)d_in[3];
    const float* bn1_b   = (const float*)d_in[4];
    const float* conv2_w = (const float*)d_in[5];
    const float* conv2_b = (const float*)d_in[6];
    const float* bn2_g   = (const float*)d_in[7];
    const float* bn2_b   = (const float*)d_in[8];
    const float* conv3_w = (const float*)d_in[9];
    const float* conv3_b = (const float*)d_in[10];
    const float* bn3_g   = (const float*)d_in[11];
    const float* bn3_b   = (const float*)d_in[12];
    const float* fr1_w   = (const float*)d_in[13];
    const float* fr1_b   = (const float*)d_in[14];
    const float* fr2_w   = (const float*)d_in[15];
    const float* fr2_b   = (const float*)d_in[16];
    const float* q_w     = (const float*)d_in[17];
    const float* h1_w    = (const float*)d_in[18];
    const float* h1_b    = (const float*)d_in[19];
    const float* bnh_g   = (const float*)d_in[20];
    const float* bnh_b   = (const float*)d_in[21];
    const float* h2_w    = (const float*)d_in[22];
    const float* h2_b    = (const float*)d_in[23];
    float* out = (float*)d_out;

    cudaFuncSetAttribute(conv2_k, cudaFuncAttributeMaxDynamicSharedMemorySize, 66048);
    cudaFuncSetAttribute(conv3_k, cudaFuncAttributeMaxDynamicSharedMemorySize, 74752);

    conv1_k<<<B, 256>>>(x, conv1_w, conv1_b, bn1_g, bn1_b);
    conv2_k<<<dim3(B, 4), 256, 66048>>>(conv2_w, conv2_b, bn2_g, bn2_b);
    conv3_k<<<dim3(B, 8), 256, 74752>>>(conv3_w, conv3_b, bn3_g, bn3_b);
    fc1_k<<<dim3(8, 16, 4), 256>>>(fr1_w);
    fc1_red<<<512, 256>>>(fr1_b);
    qprep_k<<<1, 256>>>(q_w);
    tail_k<<<B, 128>>>(fr2_w, fr2_b, h1_w, h1_b, bnh_g, bnh_b, h2_w, h2_b, out);
}

// round 9
// speedup vs baseline: 1.2247x; 1.2025x over previous
#include <cuda_runtime.h>
#include <cuda_bf16.h>
#include <math.h>

// ---------------------------------------------------------------------------
// EnhancedHybridModel: conv stack -> FC -> 4-qubit sim -> head.  B = 1024.
// conv2/conv3 use packed fp32x2 FMA (fma.rn.f32x2) paired over output chans.
// ---------------------------------------------------------------------------

#define B 1024
#define INVS 0.99999500003749968f   // 1/sqrt(1+1e-5)

typedef unsigned long long u64;

__device__ __forceinline__ u64 pk2(float lo, float hi) {
    u64 r; asm("mov.b64 %0, {%1,%2};" : "=l"(r) : "f"(lo), "f"(hi)); return r;
}
__device__ __forceinline__ float2 upk2(u64 v) {
    float2 f; asm("mov.b64 {%0,%1}, %2;" : "=f"(f.x), "=f"(f.y) : "l"(v)); return f;
}
__device__ __forceinline__ u64 fma2(u64 a, u64 b, u64 c) {
    u64 d; asm("fma.rn.f32x2 %0, %1, %2, %3;" : "=l"(d) : "l"(a), "l"(b), "l"(c)); return d;
}

__device__ float g_act1[B * 32 * 16 * 16];   // after conv1+pool
__device__ float g_act2[B * 64 * 8 * 8];     // after conv2+pool
__device__ float g_act3[B * 2048];           // after conv3+avgpool
__device__ float g_fc1p[4 * B * 512];        // fc1 split-K partials
__device__ float g_h512[B * 512];            // after FC1+ReLU
__device__ float2 g_Utot[16 * 16];           // total quantum unitary

// ---------------------------------------------------------------------------
// Kernel 1: conv1 (3->32) + BN + ReLU + maxpool.  One block per image.
// ---------------------------------------------------------------------------
__global__ __launch_bounds__(256) void conv1_k(
    const float* __restrict__ x, const float* __restrict__ w,
    const float* __restrict__ bias, const float* __restrict__ gam,
    const float* __restrict__ bet)
{
    __shared__ float sin_[3 * 34 * 34];
    __shared__ float sw_[32 * 27];
    __shared__ float sa[32], sd[32];

    const int img = blockIdx.x;
    const int tid = threadIdx.x;

    for (int i = tid; i < 3 * 34 * 34; i += 256) sin_[i] = 0.f;
    if (tid < 216) ((float4*)sw_)[tid] = ((const float4*)w)[tid];
    if (tid < 32) {
        float a = gam[tid] * INVS;
        sa[tid] = a;
        sd[tid] = a * bias[tid] + bet[tid];
    }
    __syncthreads();

    const float* xp = x + (size_t)img * 3 * 32 * 32;
    for (int i = tid; i < 3 * 32 * 32; i += 256) {
        int c = i >> 10, y = (i >> 5) & 31, xx = i & 31;
        sin_[c * (34 * 34) + (y + 1) * 34 + (xx + 1)] = xp[i];
    }
    __syncthreads();

    const int py = tid >> 4, px = tid & 15;

    float patch[3][4][4];
#pragma unroll
    for (int c = 0; c < 3; c++)
#pragma unroll
        for (int dy = 0; dy < 4; dy++)
#pragma unroll
            for (int dx = 0; dx < 4; dx++)
                patch[c][dy][dx] = sin_[c * (34 * 34) + (2 * py + dy) * 34 + (2 * px + dx)];

    float* op = g_act1 + (size_t)img * 32 * 256 + py * 16 + px;

    for (int oc = 0; oc < 32; oc++) {
        float a0 = 0.f, a1 = 0.f, a2 = 0.f, a3 = 0.f;
        const float* wk = sw_ + oc * 27;
#pragma unroll
        for (int c = 0; c < 3; c++)
#pragma unroll
            for (int ky = 0; ky < 3; ky++)
#pragma unroll
                for (int kx = 0; kx < 3; kx++) {
                    float wv = wk[c * 9 + ky * 3 + kx];
                    a0 = fmaf(patch[c][ky][kx],         wv, a0);
                    a1 = fmaf(patch[c][ky][kx + 1],     wv, a1);
                    a2 = fmaf(patch[c][ky + 1][kx],     wv, a2);
                    a3 = fmaf(patch[c][ky + 1][kx + 1], wv, a3);
                }
        float a = sa[oc], d = sd[oc];
        float v0 = fmaxf(fmaf(a, a0, d), 0.f);
        float v1 = fmaxf(fmaf(a, a1, d), 0.f);
        float v2 = fmaxf(fmaf(a, a2, d), 0.f);
        float v3 = fmaxf(fmaf(a, a3, d), 0.f);
        op[oc * 256] = fmaxf(fmaxf(v0, v1), fmaxf(v2, v3));
    }
}

// ---------------------------------------------------------------------------
// Kernel 2: conv2 (32->64) + BN + ReLU + maxpool.  f32x2 paired over ocs.
// Grid (B, 2): 32 ocs/block = 16 oc-pairs. smem: input 41472B +
// weights float2[ic=32][pair=16][kk 9->10] = 40960B -> 82432B (2 CTAs/SM).
// 256 threads: pos = tid&63, og = tid>>6 -> 4 oc-pairs each (8 ocs).
// ---------------------------------------------------------------------------
__global__ __launch_bounds__(256) void conv2_k(
    const float* __restrict__ w, const float* __restrict__ bias,
    const float* __restrict__ gam, const float* __restrict__ bet)
{
    extern __shared__ float sm[];
    float*  sin_ = sm;                        // 10368 floats
    float2* swp  = (float2*)(sm + 10368);     // [ic*160 + pair*10 + kk]
    __shared__ float sa[32], sd[32];

    const int img = blockIdx.x;
    const int ocBase = blockIdx.y * 32;
    const int tid = threadIdx.x;

    for (int i = tid; i < 10368; i += 256) sin_[i] = 0.f;
    // stage paired weights: (w[2j][ic][kk], w[2j+1][ic][kk])
    for (int i = tid; i < 16 * 32 * 9; i += 256) {
        int j = i / 288, rem = i - j * 288;
        int ic = rem / 9, kk = rem - ic * 9;
        float lo = w[(size_t)(ocBase + 2 * j) * 288 + ic * 9 + kk];
        float hi = w[(size_t)(ocBase + 2 * j + 1) * 288 + ic * 9 + kk];
        swp[ic * 160 + j * 10 + kk] = make_float2(lo, hi);
    }
    if (tid < 32) {
        int oc = ocBase + tid;
        float a = gam[oc] * INVS;
        sa[tid] = a;
        sd[tid] = a * bias[oc] + bet[oc];
    }
    __syncthreads();

    const float* ip = g_act1 + (size_t)img * 32 * 256;
    for (int i = tid; i < 32 * 256; i += 256) {
        int c = i >> 8, y = (i >> 4) & 15, xx = i & 15;
        sin_[c * 324 + (y + 1) * 18 + (xx + 1)] = ip[i];
    }
    __syncthreads();

    const int pos = tid & 63;
    const int py = pos >> 3, px = pos & 7;
    const int og = tid >> 6;          // 0..3, 4 oc-pairs each

    u64 acc[4][4];                    // [pair][pos]
#pragma unroll
    for (int j = 0; j < 4; j++)
#pragma unroll
        for (int p = 0; p < 4; p++) acc[j][p] = 0ull;

    for (int ic = 0; ic < 32; ic++) {
        // patch 4x4, each value duplicated to both f32x2 lanes
        u64 d[4][4];
        const float* sp = sin_ + ic * 324 + (2 * py) * 18 + 2 * px;
#pragma unroll
        for (int dy = 0; dy < 4; dy++) {
            float2 v0 = *(const float2*)(sp + dy * 18);
            float2 v1 = *(const float2*)(sp + dy * 18 + 2);
            d[dy][0] = pk2(v0.x, v0.x);
            d[dy][1] = pk2(v0.y, v0.y);
            d[dy][2] = pk2(v1.x, v1.x);
            d[dy][3] = pk2(v1.y, v1.y);
        }

#pragma unroll
        for (int j = 0; j < 4; j++) {
            const ulonglong2* wq =
                (const ulonglong2*)(swp + ic * 160 + (og * 4 + j) * 10);
            ulonglong2 q0 = wq[0], q1 = wq[1];   // kk0..3
            ulonglong2 q2 = wq[2];               // kk4,5
            ulonglong2 q3 = wq[3];               // kk6,7
            ulonglong2 q4 = wq[4];               // kk8, pad
            u64 wk[9] = { q0.x, q0.y, q1.x, q1.y, q2.x, q2.y, q3.x, q3.y, q4.x };
#pragma unroll
            for (int kk = 0; kk < 9; kk++) {
                int ky = kk / 3, kx = kk - ky * 3;
                acc[j][0] = fma2(d[ky][kx],         wk[kk], acc[j][0]);
                acc[j][1] = fma2(d[ky][kx + 1],     wk[kk], acc[j][1]);
                acc[j][2] = fma2(d[ky + 1][kx],     wk[kk], acc[j][2]);
                acc[j][3] = fma2(d[ky + 1][kx + 1], wk[kk], acc[j][3]);
            }
        }
    }

    float* op = g_act2 + (size_t)img * 64 * 64 + pos;
#pragma unroll
    for (int j = 0; j < 4; j++) {
        float2 v0 = upk2(acc[j][0]), v1 = upk2(acc[j][1]);
        float2 v2 = upk2(acc[j][2]), v3 = upk2(acc[j][3]);
        int lo0 = og * 8 + 2 * j, lo1 = lo0 + 1;
        {
            float a = sa[lo0], dd = sd[lo0];
            float m = fmaxf(fmaxf(fmaxf(fmaf(a, v0.x, dd), 0.f),
                                  fmaxf(fmaf(a, v1.x, dd), 0.f)),
                            fmaxf(fmaxf(fmaf(a, v2.x, dd), 0.f),
                                  fmaxf(fmaf(a, v3.x, dd), 0.f)));
            op[(ocBase + lo0) * 64] = m;
        }
        {
            float a = sa[lo1], dd = sd[lo1];
            float m = fmaxf(fmaxf(fmaxf(fmaf(a, v0.y, dd), 0.f),
                                  fmaxf(fmaf(a, v1.y, dd), 0.f)),
                            fmaxf(fmaxf(fmaf(a, v2.y, dd), 0.f),
                                  fmaxf(fmaf(a, v3.y, dd), 0.f)));
            op[(ocBase + lo1) * 64] = m;
        }
    }
}

// ---------------------------------------------------------------------------
// Kernel 3: conv3 (64->128) + BN + ReLU + avgpool.  f32x2 paired over ocs.
// Grid (B, 4): 32 ocs/block = 16 pairs, 1 pair per thread-group.
// smem: input 25600B + weights float2[64][16][10] = 81920B -> 107520B
// (2 CTAs/SM). 256 threads: pos = tid&15 (4x4 pooled), og = tid>>4.
// ---------------------------------------------------------------------------
__global__ __launch_bounds__(256) void conv3_k(
    const float* __restrict__ w, const float* __restrict__ bias,
    const float* __restrict__ gam, const float* __restrict__ bet)
{
    extern __shared__ float sm[];
    float*  sin_ = sm;                        // 6400 floats
    float2* swp  = (float2*)(sm + 6400);      // [ic*160 + pair*10 + kk]
    __shared__ float sa[32], sd[32];

    const int img = blockIdx.x;
    const int ocBase = blockIdx.y * 32;
    const int tid = threadIdx.x;

    for (int i = tid; i < 6400; i += 256) sin_[i] = 0.f;
    for (int i = tid; i < 16 * 64 * 9; i += 256) {
        int j = i / 576, rem = i - j * 576;
        int ic = rem / 9, kk = rem - ic * 9;
        float lo = w[(size_t)(ocBase + 2 * j) * 576 + ic * 9 + kk];
        float hi = w[(size_t)(ocBase + 2 * j + 1) * 576 + ic * 9 + kk];
        swp[ic * 160 + j * 10 + kk] = make_float2(lo, hi);
    }
    if (tid < 32) {
        int oc = ocBase + tid;
        float a = gam[oc] * INVS;
        sa[tid] = a;
        sd[tid] = a * bias[oc] + bet[oc];
    }
    __syncthreads();

    const float* ip = g_act2 + (size_t)img * 64 * 64;
    for (int i = tid; i < 64 * 64; i += 256) {
        int c = i >> 6, y = (i >> 3) & 7, xx = i & 7;
        sin_[c * 100 + (y + 1) * 10 + (xx + 1)] = ip[i];
    }
    __syncthreads();

    const int pos = tid & 15;
    const int py = pos >> 2, px = pos & 3;
    const int og = tid >> 4;          // 0..15, one oc-pair each

    u64 acc[4];
#pragma unroll
    for (int p = 0; p < 4; p++) acc[p] = 0ull;

    for (int ic = 0; ic < 64; ic++) {
        u64 d[4][4];
        const float* sp = sin_ + ic * 100 + (2 * py) * 10 + 2 * px;
#pragma unroll
        for (int dy = 0; dy < 4; dy++) {
            float2 v0 = *(const float2*)(sp + dy * 10);
            float2 v1 = *(const float2*)(sp + dy * 10 + 2);
            d[dy][0] = pk2(v0.x, v0.x);
            d[dy][1] = pk2(v0.y, v0.y);
            d[dy][2] = pk2(v1.x, v1.x);
            d[dy][3] = pk2(v1.y, v1.y);
        }

        const ulonglong2* wq = (const ulonglong2*)(swp + ic * 160 + og * 10);
        ulonglong2 q0 = wq[0], q1 = wq[1], q2 = wq[2], q3 = wq[3], q4 = wq[4];
        u64 wk[9] = { q0.x, q0.y, q1.x, q1.y, q2.x, q2.y, q3.x, q3.y, q4.x };
#pragma unroll
        for (int kk = 0; kk < 9; kk++) {
            int ky = kk / 3, kx = kk - ky * 3;
            acc[0] = fma2(d[ky][kx],         wk[kk], acc[0]);
            acc[1] = fma2(d[ky][kx + 1],     wk[kk], acc[1]);
            acc[2] = fma2(d[ky + 1][kx],     wk[kk], acc[2]);
            acc[3] = fma2(d[ky + 1][kx + 1], wk[kk], acc[3]);
        }
    }

    {
        float2 v0 = upk2(acc[0]), v1 = upk2(acc[1]);
        float2 v2 = upk2(acc[2]), v3 = upk2(acc[3]);
        int lo0 = 2 * og, lo1 = lo0 + 1;
        float a = sa[lo0], dd = sd[lo0];
        float s = fmaxf(fmaf(a, v0.x, dd), 0.f) + fmaxf(fmaf(a, v1.x, dd), 0.f)
                + fmaxf(fmaf(a, v2.x, dd), 0.f) + fmaxf(fmaf(a, v3.x, dd), 0.f);
        g_act3[(size_t)img * 2048 + (ocBase + lo0) * 16 + pos] = 0.25f * s;
        a = sa[lo1]; dd = sd[lo1];
        s = fmaxf(fmaf(a, v0.y, dd), 0.f) + fmaxf(fmaf(a, v1.y, dd), 0.f)
          + fmaxf(fmaf(a, v2.y, dd), 0.f) + fmaxf(fmaf(a, v3.y, dd), 0.f);
        g_act3[(size_t)img * 2048 + (ocBase + lo1) * 16 + pos] = 0.25f * s;
    }
}

// ---------------------------------------------------------------------------
// Kernel 4a: FC1 split-K partial.  grid (8, 16, 4): 512 CTAs.
// ---------------------------------------------------------------------------
__global__ __launch_bounds__(256) void fc1_k(const float* __restrict__ W)
{
    __shared__ float As[16 * 68];
    __shared__ float Bs[16 * 68];

    const int obase = blockIdx.x * 64;
    const int nbase = blockIdx.y * 64;
    const int kz    = blockIdx.z;
    const int tid = threadIdx.x;
    const int ty = tid >> 4, tx = tid & 15;

    const int lr = tid >> 2;
    const int lc = (tid & 3) * 4;

    float acc[4][4];
#pragma unroll
    for (int i = 0; i < 4; i++)
#pragma unroll
        for (int j = 0; j < 4; j++) acc[i][j] = 0.f;

    const int kbeg = kz * 512, kend = kbeg + 512;
    for (int k0 = kbeg; k0 < kend; k0 += 16) {
        float4 av = *(const float4*)(g_act3 + (size_t)(nbase + lr) * 2048 + k0 + lc);
        float4 bv = *(const float4*)(W + (size_t)(obase + lr) * 2048 + k0 + lc);
        As[(lc + 0) * 68 + lr] = av.x;
        As[(lc + 1) * 68 + lr] = av.y;
        As[(lc + 2) * 68 + lr] = av.z;
        As[(lc + 3) * 68 + lr] = av.w;
        Bs[(lc + 0) * 68 + lr] = bv.x;
        Bs[(lc + 1) * 68 + lr] = bv.y;
        Bs[(lc + 2) * 68 + lr] = bv.z;
        Bs[(lc + 3) * 68 + lr] = bv.w;
        __syncthreads();
#pragma unroll
        for (int kk = 0; kk < 16; kk++) {
            float4 a = *(const float4*)&As[kk * 68 + ty * 4];
            float4 b = *(const float4*)&Bs[kk * 68 + tx * 4];
            acc[0][0] = fmaf(a.x, b.x, acc[0][0]);
            acc[0][1] = fmaf(a.x, b.y, acc[0][1]);
            acc[0][2] = fmaf(a.x, b.z, acc[0][2]);
            acc[0][3] = fmaf(a.x, b.w, acc[0][3]);
            acc[1][0] = fmaf(a.y, b.x, acc[1][0]);
            acc[1][1] = fmaf(a.y, b.y, acc[1][1]);
            acc[1][2] = fmaf(a.y, b.z, acc[1][2]);
            acc[1][3] = fmaf(a.y, b.w, acc[1][3]);
            acc[2][0] = fmaf(a.z, b.x, acc[2][0]);
            acc[2][1] = fmaf(a.z, b.y, acc[2][1]);
            acc[2][2] = fmaf(a.z, b.z, acc[2][2]);
            acc[2][3] = fmaf(a.z, b.w, acc[2][3]);
            acc[3][0] = fmaf(a.w, b.x, acc[3][0]);
            acc[3][1] = fmaf(a.w, b.y, acc[3][1]);
            acc[3][2] = fmaf(a.w, b.z, acc[3][2]);
            acc[3][3] = fmaf(a.w, b.w, acc[3][3]);
        }
        __syncthreads();
    }

    float* pp = g_fc1p + (size_t)kz * B * 512;
#pragma unroll
    for (int i = 0; i < 4; i++) {
        int n = nbase + ty * 4 + i;
#pragma unroll
        for (int j = 0; j < 4; j++) {
            int o = obase + tx * 4 + j;
            pp[(size_t)n * 512 + o] = acc[i][j];
        }
    }
}

// ---------------------------------------------------------------------------
// Kernel 4b: FC1 reduce.
// ---------------------------------------------------------------------------
__global__ __launch_bounds__(256) void fc1_red(const float* __restrict__ bias)
{
    const int idx = blockIdx.x * 256 + threadIdx.x;
    const int e0 = idx * 4;
    const int o = e0 & 511;

    float4 s0 = *(const float4*)(g_fc1p + e0);
    float4 s1 = *(const float4*)(g_fc1p + (size_t)B * 512 + e0);
    float4 s2 = *(const float4*)(g_fc1p + (size_t)2 * B * 512 + e0);
    float4 s3 = *(const float4*)(g_fc1p + (size_t)3 * B * 512 + e0);
    float4 bv = *(const float4*)(bias + o);

    float4 r;
    r.x = fmaxf(s0.x + s1.x + s2.x + s3.x + bv.x, 0.f);
    r.y = fmaxf(s0.y + s1.y + s2.y + s3.y + bv.y, 0.f);
    r.z = fmaxf(s0.z + s1.z + s2.z + s3.z + bv.z, 0.f);
    r.w = fmaxf(s0.w + s1.w + s2.w + s3.w + bv.w, 0.f);
    *(float4*)(g_h512 + e0) = r;
}

// ---------------------------------------------------------------------------
// Kernel 5: build total 16x16 complex unitary from q_weights.
// ---------------------------------------------------------------------------
__global__ void qprep_k(const float* __restrict__ qw)
{
    __shared__ float2 U1[256], U2[256];
    const int tid = threadIdx.x;
    const int i = tid >> 4, j = tid & 15;

    for (int l = 0; l < 2; l++) {
        float re = 1.f, im = 0.f;
#pragma unroll
        for (int q = 0; q < 4; q++) {
            float th = qw[l * 4 + q] * 0.5f;
            float c = cosf(th), s = sinf(th);
            int bi = (i >> (3 - q)) & 1, bj = (j >> (3 - q)) & 1;
            if (bi == bj) { re *= c; im *= c; }
            else { float nr = im * s, ni = -re * s; re = nr; im = ni; }
        }
        int bb = i;
        if ((bb >> 3) & 1) bb ^= 4;
        if ((bb >> 2) & 1) bb ^= 2;
        if ((bb >> 1) & 1) bb ^= 1;
        if (bb & 1)        bb ^= 8;
        float2 v = make_float2(re, im);
        if (l == 0) U1[bb * 16 + j] = v; else U2[bb * 16 + j] = v;
    }
    __syncthreads();

    float ar = 0.f, ai = 0.f;
#pragma unroll
    for (int k = 0; k < 16; k++) {
        float2 a = U2[i * 16 + k], b = U1[k * 16 + j];
        ar += a.x * b.x - a.y * b.y;
        ai += a.x * b.y + a.y * b.x;
    }
    g_Utot[tid] = make_float2(ar, ai);
}

// ---------------------------------------------------------------------------
// Kernel 6: fused tail per sample. grid B, 128 threads.
// ---------------------------------------------------------------------------
__global__ __launch_bounds__(128) void tail_k(
    const float* __restrict__ fr2w, const float* __restrict__ fr2b,
    const float* __restrict__ h1w,  const float* __restrict__ h1b,
    const float* __restrict__ bnhg, const float* __restrict__ bnhb,
    const float* __restrict__ h2w,  const float* __restrict__ h2b,
    float* __restrict__ out)
{
    __shared__ float sh[512];
    __shared__ float2 sU[256];
    __shared__ float logits[16];
    __shared__ float psi[16];
    __shared__ float probs[16];
    __shared__ float qv[4];
    __shared__ float t1[128];

    const int bimg = blockIdx.x;
    const int tid = threadIdx.x;

    const float* hp = g_h512 + (size_t)bimg * 512;
    for (int i = tid; i < 512; i += 128) sh[i] = hp[i];
    sU[tid] = g_Utot[tid];
    sU[tid + 128] = g_Utot[tid + 128];
    __syncthreads();

    {
        int o = tid >> 3, c = tid & 7;
        const float* wr = fr2w + (size_t)o * 512 + c * 64;
        const float* hr = sh + c * 64;
        float s = 0.f;
#pragma unroll 8
        for (int k = 0; k < 64; k++) s = fmaf(hr[k], wr[k], s);
        s += __shfl_xor_sync(0xffffffffu, s, 4, 8);
        s += __shfl_xor_sync(0xffffffffu, s, 2, 8);
        s += __shfl_xor_sync(0xffffffffu, s, 1, 8);
        if (c == 0) logits[o] = s + fr2b[o];
    }
    __syncthreads();

    if (tid < 16) {
        float v = logits[tid];
        float m = v;
#pragma unroll
        for (int off = 8; off > 0; off >>= 1)
            m = fmaxf(m, __shfl_xor_sync(0x0000ffffu, m, off, 16));
        float e = expf(v - m);
        float sum = e;
#pragma unroll
        for (int off = 8; off > 0; off >>= 1)
            sum += __shfl_xor_sync(0x0000ffffu, sum, off, 16);
        float f = e / sum;
        float s2 = f * f;
#pragma unroll
        for (int off = 8; off > 0; off >>= 1)
            s2 += __shfl_xor_sync(0x0000ffffu, s2, off, 16);
        psi[tid] = f / sqrtf(s2);
    }
    __syncthreads();

    if (tid < 16) {
        float yr = 0.f, yi = 0.f;
#pragma unroll
        for (int jj = 0; jj < 16; jj++) {
            float2 u = sU[tid * 16 + jj];
            float p = psi[jj];
            yr = fmaf(u.x, p, yr);
            yi = fmaf(u.y, p, yi);
        }
        probs[tid] = yr * yr + yi * yi;
    }
    __syncthreads();

    if (tid < 4) {
        float e = 0.f;
#pragma unroll
        for (int bb = 0; bb < 16; bb++) {
            float z = 1.f - 2.f * (float)((bb >> (3 - tid)) & 1);
            e = fmaf(probs[bb], z, e);
        }
        qv[tid] = e;
    }
    __syncthreads();

    {
        float v = h1b[tid];
#pragma unroll
        for (int k = 0; k < 4; k++) v = fmaf(h1w[tid * 4 + k], qv[k], v);
        v = fmaf(bnhg[tid] * INVS, v, bnhb[tid]);
        t1[tid] = fmaxf(v, 0.f);
    }
    __syncthreads();

    if (tid < 100) {
        const float* wr = h2w + (size_t)tid * 128;
        float s = h2b[tid];
#pragma unroll 8
        for (int jj = 0; jj < 128; jj++) s = fmaf(t1[jj], wr[jj], s);
        out[(size_t)bimg * 100 + tid] = s;
    }
}

// ---------------------------------------------------------------------------
// Launch
// ---------------------------------------------------------------------------
extern "C" void kernel_launch(void* const* d_in, const int* in_sizes, int n_in,
                              void* d_out, int out_size)
{
    const float* x       = (const float*)d_in[0];
    const float* conv1_w = (const float*)d_in[1];
    const float* conv1_b = (const float*)d_in[2];
    const float* bn1_g   = (const float*)d_in[3];
    const float* bn1_b   = (const float*)d_in[4];
    const float* conv2_w = (const float*)d_in[5];
    const float* conv2_b = (const float*)d_in[6];
    const float* bn2_g   = (const float*)d_in[7];
    const float* bn2_b   = (const float*)d_in[8];
    const float* conv3_w = (const float*)d_in[9];
    const float* conv3_b = (const float*)d_in[10];
    const float* bn3_g   = (const float*)d_in[11];
    const float* bn3_b   = (const float*)d_in[12];
    const float* fr1_w   = (const float*)d_in[13];
    const float* fr1_b   = (const float*)d_in[14];
    const float* fr2_w   = (const float*)d_in[15];
    const float* fr2_b   = (const float*)d_in[16];
    const float* q_w     = (const float*)d_in[17];
    const float* h1_w    = (const float*)d_in[18];
    const float* h1_b    = (const float*)d_in[19];
    const float* bnh_g   = (const float*)d_in[20];
    const float* bnh_b   = (const float*)d_in[21];
    const float* h2_w    = (const float*)d_in[22];
    const float* h2_b    = (const float*)d_in[23];
    float* out = (float*)d_out;

    cudaFuncSetAttribute(conv2_k, cudaFuncAttributeMaxDynamicSharedMemorySize, 82432);
    cudaFuncSetAttribute(conv3_k, cudaFuncAttributeMaxDynamicSharedMemorySize, 107520);

    conv1_k<<<B, 256>>>(x, conv1_w, conv1_b, bn1_g, bn1_b);
    conv2_k<<<dim3(B, 2), 256, 82432>>>(conv2_w, conv2_b, bn2_g, bn2_b);
    conv3_k<<<dim3(B, 4), 256, 107520>>>(conv3_w, conv3_b, bn3_g, bn3_b);
    fc1_k<<<dim3(8, 16, 4), 256>>>(fr1_w);
    fc1_red<<<512, 256>>>(fr1_b);
    qprep_k<<<1, 256>>>(q_w);
    tail_k<<<B, 128>>>(fr2_w, fr2_b, h1_w, h1_b, bnh_g, bnh_b, h2_w, h2_b, out);
}